// round 1
// baseline (speedup 1.0000x reference)
#include <cuda_runtime.h>
#include <cuda_bf16.h>
#include <cstdint>

// Problem constants (fixed by the dataset)
#define BB 16
#define TT 4096
#define CC 128

// Scratch (no cudaMalloc allowed): transition matrix P=exp(log_softmax(log_trans)),
// its transpose, and the beta lattice.
__device__ float g_P[CC * CC];
__device__ float g_PT[CC * CC];
__device__ float g_beta[(size_t)BB * TT * CC];

// ---------------------------------------------------------------------------
// Kernel 1: P = softmax(log_trans, axis=1), plus transpose.
// 128 blocks (one per row) x 128 threads.
// ---------------------------------------------------------------------------
__global__ void __launch_bounds__(CC) prep_kernel(const float* __restrict__ LT)
{
    const int i = blockIdx.x;
    const int j = threadIdx.x;
    const float v = LT[i * CC + j];

    __shared__ float redm[4];
    __shared__ float reds[4];

    // row max
    float m = v;
    #pragma unroll
    for (int o = 16; o; o >>= 1) m = fmaxf(m, __shfl_xor_sync(0xffffffffu, m, o));
    if ((j & 31) == 0) redm[j >> 5] = m;
    __syncthreads();
    m = fmaxf(fmaxf(redm[0], redm[1]), fmaxf(redm[2], redm[3]));

    // row sum of exp
    const float e = __expf(v - m);
    float s = e;
    #pragma unroll
    for (int o = 16; o; o >>= 1) s += __shfl_xor_sync(0xffffffffu, s, o);
    if ((j & 31) == 0) reds[j >> 5] = s;
    __syncthreads();
    s = reds[0] + reds[1] + reds[2] + reds[3];

    const float pv = e / s;        // P[i][j] = exp(lt[i][j]),  lt = log_softmax row
    g_P [i * CC + j] = pv;
    g_PT[j * CC + i] = pv;
}

// ---------------------------------------------------------------------------
// Kernel 2: forward/backward scans. 32 blocks (16 fwd + 16 bwd), 128 threads.
// Each block owns one (batch, direction) chain; the per-step LSE-matvec is a
// real fp32 matvec against a register-resident P column, with a running scale m.
//   forward:  alpha_t[j] = u_t[j] + m + log( sum_i exp(alpha_{t-1}[i]-m) P[i][j] )
//   backward: beta_t[i]  =          m + log( sum_j exp(c_j - m) P[i][j] ),
//             c_j = beta_{t+1}[j] + u_{t+1}[j]
// alpha is written into d_out; beta into g_beta.
// ---------------------------------------------------------------------------
__global__ void __launch_bounds__(CC, 1) scan_kernel(const float* __restrict__ U,
                                                     float* __restrict__ Alpha)
{
    const int tid = threadIdx.x;
    const int b   = blockIdx.x & 15;
    const bool bwd = blockIdx.x >= 16;

    __shared__ __align__(16) float sv[CC];
    __shared__ float sm;

    // Register-resident matrix column.
    // forward : p[i] = P[i][tid]   (thread tid computes output state tid; sum over i)
    // backward: p[j] = PT[j][tid] = P[tid][j] (thread tid computes state tid; sum over j)
    float p[CC];
    {
        const float* __restrict__ M = bwd ? g_PT : g_P;
        #pragma unroll
        for (int i = 0; i < CC; i++) p[i] = M[i * CC + tid];
    }

    const size_t baseU = (size_t)b * TT * CC;
    const float* __restrict__ Ub = U + baseU;

    if (!bwd) {
        // ---------------- forward ----------------
        float a = Ub[tid];                       // alpha_0 = u_0
        Alpha[baseU + tid] = a;
        if (tid == 0) sm = a;
        __syncthreads();
        float m = sm;
        sv[tid] = __expf(a - m);
        __syncthreads();

        float u_cur = Ub[(size_t)CC + tid];      // u at t=1
        for (int t = 1; t < TT; ++t) {
            // prefetch next step's u
            float u_next = 0.0f;
            if (t + 1 < TT) u_next = Ub[(size_t)(t + 1) * CC + tid];

            float acc0 = 0.f, acc1 = 0.f, acc2 = 0.f, acc3 = 0.f;
            #pragma unroll
            for (int i = 0; i < CC; i += 4) {
                const float4 v4 = *(const float4*)(sv + i);   // broadcast LDS.128
                acc0 = fmaf(v4.x, p[i + 0], acc0);
                acc1 = fmaf(v4.y, p[i + 1], acc1);
                acc2 = fmaf(v4.z, p[i + 2], acc2);
                acc3 = fmaf(v4.w, p[i + 3], acc3);
            }
            const float w = (acc0 + acc1) + (acc2 + acc3);

            const float a2 = u_cur + m + __logf(w);
            Alpha[baseU + (size_t)t * CC + tid] = a2;

            if (tid == 0) sm = a2;
            __syncthreads();                     // sm visible; all readers done with sv
            const float mn = sm;
            sv[tid] = __expf(a2 - mn);
            m = mn;
            __syncthreads();                     // sv ready for next step

            u_cur = u_next;
        }
    } else {
        // ---------------- backward ----------------
        float* __restrict__ Beta = g_beta;
        Beta[baseU + (size_t)(TT - 1) * CC + tid] = 0.0f;    // beta_{T-1} = 0

        float c = Ub[(size_t)(TT - 1) * CC + tid];           // c = beta_{T-1} + u_{T-1}
        if (tid == 0) sm = c;
        __syncthreads();
        float m = sm;
        sv[tid] = __expf(c - m);
        __syncthreads();

        float u_cur = Ub[(size_t)(TT - 2) * CC + tid];       // u at t=T-2
        for (int t = TT - 2; t >= 0; --t) {
            float u_next = 0.0f;
            if (t > 0) u_next = Ub[(size_t)(t - 1) * CC + tid];

            float acc0 = 0.f, acc1 = 0.f, acc2 = 0.f, acc3 = 0.f;
            #pragma unroll
            for (int j = 0; j < CC; j += 4) {
                const float4 v4 = *(const float4*)(sv + j);
                acc0 = fmaf(v4.x, p[j + 0], acc0);
                acc1 = fmaf(v4.y, p[j + 1], acc1);
                acc2 = fmaf(v4.z, p[j + 2], acc2);
                acc3 = fmaf(v4.w, p[j + 3], acc3);
            }
            const float w = (acc0 + acc1) + (acc2 + acc3);

            const float bt = m + __logf(w);                  // beta_t[tid]
            Beta[baseU + (size_t)t * CC + tid] = bt;

            const float c2 = bt + u_cur;                     // c for next (earlier) step
            if (tid == 0) sm = c2;
            __syncthreads();
            const float mn = sm;
            sv[tid] = __expf(c2 - mn);
            m = mn;
            __syncthreads();

            u_cur = u_next;
        }
    }
}

// ---------------------------------------------------------------------------
// Kernel 3: out = log_softmax(alpha + beta, axis=-1). One warp per (b,t) row,
// 4 elements per lane via float4. Memory bound.
// ---------------------------------------------------------------------------
__global__ void __launch_bounds__(256) final_kernel(float* __restrict__ Out)
{
    const int warp = blockIdx.x * (blockDim.x >> 5) + (threadIdx.x >> 5);
    const int lane = threadIdx.x & 31;
    const size_t base = (size_t)warp * CC + lane * 4;

    const float4 a4 = *(const float4*)(Out + base);
    const float4 b4 = *(const float4*)(g_beta + base);
    const float s0 = a4.x + b4.x;
    const float s1 = a4.y + b4.y;
    const float s2 = a4.z + b4.z;
    const float s3 = a4.w + b4.w;

    float m = fmaxf(fmaxf(s0, s1), fmaxf(s2, s3));
    #pragma unroll
    for (int o = 16; o; o >>= 1) m = fmaxf(m, __shfl_xor_sync(0xffffffffu, m, o));

    float e = __expf(s0 - m) + __expf(s1 - m) + __expf(s2 - m) + __expf(s3 - m);
    #pragma unroll
    for (int o = 16; o; o >>= 1) e += __shfl_xor_sync(0xffffffffu, e, o);

    const float lse = m + __logf(e);
    float4 o4;
    o4.x = s0 - lse; o4.y = s1 - lse; o4.z = s2 - lse; o4.w = s3 - lse;
    *(float4*)(Out + base) = o4;
}

// ---------------------------------------------------------------------------
// Launch
// ---------------------------------------------------------------------------
extern "C" void kernel_launch(void* const* d_in, const int* in_sizes, int n_in,
                              void* d_out, int out_size)
{
    const float* U  = (const float*)d_in[0];   // unary_logits (B,T,C) fp32
    const float* LT = (const float*)d_in[1];   // log_trans (C,C) fp32
    float* out = (float*)d_out;                // (B,T,C) fp32

    prep_kernel<<<CC, CC>>>(LT);
    scan_kernel<<<2 * BB, CC>>>(U, out);
    // B*T = 65536 rows, 8 warps/block -> 8192 blocks
    final_kernel<<<(BB * TT) / 8, 256>>>(out);
}